// round 8
// baseline (speedup 1.0000x reference)
#include <cuda_runtime.h>
#include <math_constants.h>

// BarycentricPooling — closed form (R1 derivation):
// After the final g-half-step the transport plan's second marginal equals
// b = softmax(log_prior) exactly; hist[n,:] == b for all n, segment-mean of
// identical rows is b, empty-graph fallback is b.
// Output [B=256, K=64] = softmax(log_codebook_prior) broadcast over rows.
//
// R8: CTA-count lever confirmed real in R7 (32->8 CTAs: 4.32->3.94us ncu).
// Push to the endpoint: 4 CTAs x 1024 threads, one float4 per thread,
// identical instruction chain. Per thread: 1 LDG.128 of its own chunk,
// 1 broadcast SHFL (common softmax shift — exact by shift-invariance),
// 4 MUFU exp, 4-step butterfly over 16-lane groups (each chunk appears
// twice per warp, so the group sum is the exact total), RCP, 1 STG.128.

__global__ void __launch_bounds__(1024, 1)
prior_broadcast_kernel(const float4* __restrict__ lp4,
                       float4* __restrict__ out4) {
    const int i = blockIdx.x * blockDim.x + threadIdx.x;
    const int j = i & 15;                 // chunk index, ready before the load

    float4 v = lp4[j];                    // one LDG.128 (L1/L2 broadcast)

    // Warp-uniform shift: lane 0's local max (any common constant is exact).
    float lm = fmaxf(fmaxf(v.x, v.y), fmaxf(v.z, v.w));
    float shift = __shfl_sync(0xffffffff, lm, 0);

    float e0 = __expf(v.x - shift);
    float e1 = __expf(v.y - shift);
    float e2 = __expf(v.z - shift);
    float e3 = __expf(v.w - shift);
    float s = (e0 + e1) + (e2 + e3);

    // Lanes j and j+16 hold identical chunks: reduce within 16-lane groups.
    #pragma unroll
    for (int o = 8; o > 0; o >>= 1)
        s += __shfl_xor_sync(0xffffffff, s, o);

    float inv = __frcp_rn(s);
    out4[i] = make_float4(e0 * inv, e1 * inv, e2 * inv, e3 * inv);
}

// Generic fallback (any K / size) — never taken for this problem shape.
__global__ void prior_broadcast_generic(const float* __restrict__ log_prior,
                                        float* __restrict__ out,
                                        int K, int total) {
    extern __shared__ float soft[];
    const int tid = threadIdx.x;
    if (tid < K) {
        float m = -CUDART_INF_F;
        for (int j = 0; j < K; ++j) m = fmaxf(m, log_prior[j]);
        float s = 0.0f;
        for (int j = 0; j < K; ++j) s += __expf(log_prior[j] - m);
        soft[tid] = __expf(log_prior[tid] - m) / s;
    }
    __syncthreads();
    for (int i = blockIdx.x * blockDim.x + tid; i < total;
         i += gridDim.x * blockDim.x)
        out[i] = soft[i % K];
}

extern "C" void kernel_launch(void* const* d_in, const int* in_sizes, int n_in,
                              void* d_out, int out_size) {
    // metadata order: node_distributions, batch_idx, codebook, log_codebook_prior
    const float* log_prior = (const float*)d_in[3];
    const int K = in_sizes[3];  // 64

    const int threads = 1024;
    if (K == 64 && (out_size & (4 * threads - 1)) == 0) {
        int total4 = out_size >> 2;          // 4096
        int blocks = total4 / threads;       // 4 — exact cover, no tail
        prior_broadcast_kernel<<<blocks, threads>>>(
            (const float4*)log_prior, (float4*)d_out);
    } else {
        const int t2 = 256;
        int blocks = (out_size + t2 - 1) / t2;
        if (blocks > 64) blocks = 64;
        if (blocks < 1) blocks = 1;
        prior_broadcast_generic<<<blocks, t2, (size_t)K * sizeof(float)>>>(
            log_prior, (float*)d_out, K, out_size);
    }
}

// round 9
// speedup vs baseline: 1.4894x; 1.4894x over previous
#include <cuda_runtime.h>
#include <math_constants.h>

// BarycentricPooling — closed form (R1 derivation):
// After the final g-half-step the transport plan's second marginal equals
// b = softmax(log_prior) exactly; hist[n,:] == b for all n, segment-mean of
// identical rows is b, empty-graph fallback is b.
// Output [B=256, K=64] = softmax(log_codebook_prior) broadcast over rows.
//
// R9 = R7 (champion, confirmation rebench). CTA-count curve measured:
// 32 CTAs: 4.32us, 8: 3.94us, 4: 4.35us (ncu) — minimum at 8x512.
// Per thread: 1 LDG.128 of its own chunk, 1 broadcast SHFL (common softmax
// shift — exact by shift-invariance), 4 MUFU exp, 4-step butterfly over
// 16-lane groups (each chunk appears twice per warp, so the group sum is the
// exact total), RCP, 1 STG.128. Everything beyond ~450 cycles is launch floor.

__global__ void __launch_bounds__(512, 1)
prior_broadcast_kernel(const float4* __restrict__ lp4,
                       float4* __restrict__ out4) {
    const int i = blockIdx.x * blockDim.x + threadIdx.x;
    const int j = i & 15;                 // chunk index, ready before the load

    float4 v = lp4[j];                    // one LDG.128 (L1/L2 broadcast)

    // Warp-uniform shift: lane 0's local max (any common constant is exact).
    float lm = fmaxf(fmaxf(v.x, v.y), fmaxf(v.z, v.w));
    float shift = __shfl_sync(0xffffffff, lm, 0);

    float e0 = __expf(v.x - shift);
    float e1 = __expf(v.y - shift);
    float e2 = __expf(v.z - shift);
    float e3 = __expf(v.w - shift);
    float s = (e0 + e1) + (e2 + e3);

    // Lanes j and j+16 hold identical chunks: reduce within 16-lane groups.
    #pragma unroll
    for (int o = 8; o > 0; o >>= 1)
        s += __shfl_xor_sync(0xffffffff, s, o);

    float inv = __frcp_rn(s);
    out4[i] = make_float4(e0 * inv, e1 * inv, e2 * inv, e3 * inv);
}

// Generic fallback (any K / size) — never taken for this problem shape.
__global__ void prior_broadcast_generic(const float* __restrict__ log_prior,
                                        float* __restrict__ out,
                                        int K, int total) {
    extern __shared__ float soft[];
    const int tid = threadIdx.x;
    if (tid < K) {
        float m = -CUDART_INF_F;
        for (int j = 0; j < K; ++j) m = fmaxf(m, log_prior[j]);
        float s = 0.0f;
        for (int j = 0; j < K; ++j) s += __expf(log_prior[j] - m);
        soft[tid] = __expf(log_prior[tid] - m) / s;
    }
    __syncthreads();
    for (int i = blockIdx.x * blockDim.x + tid; i < total;
         i += gridDim.x * blockDim.x)
        out[i] = soft[i % K];
}

extern "C" void kernel_launch(void* const* d_in, const int* in_sizes, int n_in,
                              void* d_out, int out_size) {
    // metadata order: node_distributions, batch_idx, codebook, log_codebook_prior
    const float* log_prior = (const float*)d_in[3];
    const int K = in_sizes[3];  // 64

    const int threads = 512;
    if (K == 64 && (out_size & (4 * threads - 1)) == 0) {
        int total4 = out_size >> 2;          // 4096
        int blocks = total4 / threads;       // 8 — exact cover, no tail
        prior_broadcast_kernel<<<blocks, threads>>>(
            (const float4*)log_prior, (float4*)d_out);
    } else {
        const int t2 = 256;
        int blocks = (out_size + t2 - 1) / t2;
        if (blocks > 64) blocks = 64;
        if (blocks < 1) blocks = 1;
        prior_broadcast_generic<<<blocks, t2, (size_t)K * sizeof(float)>>>(
            log_prior, (float*)d_out, K, out_size);
    }
}